// round 5
// baseline (speedup 1.0000x reference)
#include <cuda_runtime.h>
#include <math.h>
#include <stdint.h>

// ---------------------------------------------------------------------------
// LSTM: B=128, T=256, In=512, H=1024, Out=512
// Phase 0: pack gate weights PLANAR  n = g*1024 + j  (g: 0=f,1=i,2=c,3=o)
// Phase 1: GX[m, n] = x[m,:] . Wxp[n,:] + bp[n]   (fp32 SGEMM, m = b*256 + t)
// Phase 2: ONE persistent kernel, 256 timesteps, W slice resident in SMEM,
//          tf32 mma + fused gate epilogue + software grid barrier per step.
// Phase 3: out[m, o] = HS[m,:] . W_out[o,:] + b_out[o]  (fp32 SGEMM)
// ---------------------------------------------------------------------------

#define B_   128
#define T_   256
#define IN_  512
#define H_   1024
#define G4_  4096
#define OUT_ 512
#define M_   (B_ * T_)      // 32768

#define NBLK    128         // persistent grid (<148 SMs, 1 block/SM)
#define CHUNK   64          // k-chunk for h staging
#define WSTRIDE 1028        // 1024 + 4 pad (stride%32==4 -> conflict-free)
#define HSTRIDE 68          // 64 + 4 pad
#define SMEM_WORDS (32 * WSTRIDE + 128 * HSTRIDE)
#define SMEM_BYTES (SMEM_WORDS * 4)

__device__ float    g_Wxp[(size_t)G4_ * IN_];   // packed x-part weights (fp32)
__device__ uint32_t g_Whp[(size_t)G4_ * H_];    // packed h-part weights (tf32 bits)
__device__ float    g_bp [G4_];                 // packed bias
__device__ float    g_GX [(size_t)M_ * G4_];    // input-projection gates
__device__ float    g_HS [(size_t)M_ * H_];     // hidden states (all t)
__device__ float    g_h  [2][B_ * H_];          // ping-pong h
__device__ float    g_c  [B_ * H_];             // cell state
__device__ unsigned g_bar;                      // grid-barrier counter

__device__ __forceinline__ float sigmf(float x) { return 1.0f / (1.0f + expf(-x)); }

__device__ __forceinline__ uint32_t f2tf32(float x) {
    uint32_t r;
    asm("cvt.rna.tf32.f32 %0, %1;" : "=r"(r) : "f"(x));
    return r;
}

__device__ __forceinline__ void mma_tf32(float c[4], uint32_t a0, uint32_t a1,
                                         uint32_t a2, uint32_t a3,
                                         uint32_t b0, uint32_t b1) {
    asm volatile(
        "mma.sync.aligned.m16n8k8.row.col.f32.tf32.tf32.f32 "
        "{%0,%1,%2,%3}, {%4,%5,%6,%7}, {%8,%9}, {%0,%1,%2,%3};"
        : "+f"(c[0]), "+f"(c[1]), "+f"(c[2]), "+f"(c[3])
        : "r"(a0), "r"(a1), "r"(a2), "r"(a3), "r"(b0), "r"(b1));
}

// ---------------------------------------------------------------------------
// Phase 0: pack weights planar. blockIdx.x = n (0..4095). 128 threads.
// ---------------------------------------------------------------------------
__global__ void pack_weights(const float* __restrict__ Wf, const float* __restrict__ Wi,
                             const float* __restrict__ Wc, const float* __restrict__ Wo,
                             const float* __restrict__ bf, const float* __restrict__ bi,
                             const float* __restrict__ bc, const float* __restrict__ bo)
{
    int n = blockIdx.x;
    int g = n >> 10;
    int j = n & 1023;
    const float* W = (g == 0) ? Wf : (g == 1) ? Wi : (g == 2) ? Wc : Wo;
    const float* row = W + (size_t)j * (IN_ + H_);
    for (int k = threadIdx.x; k < IN_; k += blockDim.x)
        g_Wxp[(size_t)n * IN_ + k] = row[k];
    for (int k = threadIdx.x; k < H_; k += blockDim.x)
        g_Whp[(size_t)n * H_ + k] = f2tf32(row[IN_ + k]);
    if (threadIdx.x == 0) {
        const float* bb = (g == 0) ? bf : (g == 1) ? bi : (g == 2) ? bc : bo;
        g_bp[n] = bb[j];
    }
}

// ---------------------------------------------------------------------------
// Generic NT SGEMM: C[M,N] = A[M,K] * B[N,K]^T + bias[N]   (fp32)
// ---------------------------------------------------------------------------
__global__ void __launch_bounds__(256)
sgemm_nt(const float* __restrict__ A, const float* __restrict__ Bm,
         const float* __restrict__ bias, float* __restrict__ C,
         int Mdim, int Ndim, int Kdim)
{
    __shared__ float As[8][128];
    __shared__ float Bs[8][128];

    const int tid = threadIdx.x;
    const int m0 = blockIdx.y * 128;
    const int n0 = blockIdx.x * 128;

    const int ldRow = tid >> 1;
    const int ldK   = (tid & 1) * 4;

    const float* Aptr = A + (size_t)(m0 + ldRow) * Kdim + ldK;
    const float* Bptr = Bm + (size_t)(n0 + ldRow) * Kdim + ldK;

    const int ty = tid >> 4;
    const int tx = tid & 15;

    float acc[8][8];
#pragma unroll
    for (int i = 0; i < 8; i++)
#pragma unroll
        for (int j = 0; j < 8; j++) acc[i][j] = 0.0f;

    for (int k0 = 0; k0 < Kdim; k0 += 8) {
        float4 av = *(const float4*)(Aptr + k0);
        float4 bv = *(const float4*)(Bptr + k0);
        As[ldK + 0][ldRow] = av.x;
        As[ldK + 1][ldRow] = av.y;
        As[ldK + 2][ldRow] = av.z;
        As[ldK + 3][ldRow] = av.w;
        Bs[ldK + 0][ldRow] = bv.x;
        Bs[ldK + 1][ldRow] = bv.y;
        Bs[ldK + 2][ldRow] = bv.z;
        Bs[ldK + 3][ldRow] = bv.w;
        __syncthreads();

#pragma unroll
        for (int kk = 0; kk < 8; kk++) {
            float ar[8], br[8];
            *(float4*)(ar)     = *(const float4*)&As[kk][ty * 8];
            *(float4*)(ar + 4) = *(const float4*)&As[kk][ty * 8 + 4];
            *(float4*)(br)     = *(const float4*)&Bs[kk][tx * 8];
            *(float4*)(br + 4) = *(const float4*)&Bs[kk][tx * 8 + 4];
#pragma unroll
            for (int i = 0; i < 8; i++)
#pragma unroll
                for (int j = 0; j < 8; j++)
                    acc[i][j] = fmaf(ar[i], br[j], acc[i][j]);
        }
        __syncthreads();
    }

#pragma unroll
    for (int i = 0; i < 8; i++) {
        float* crow = C + (size_t)(m0 + ty * 8 + i) * Ndim + n0 + tx * 8;
        const float* brow = bias + n0 + tx * 8;
        float4 v0, v1;
        v0.x = acc[i][0] + brow[0];
        v0.y = acc[i][1] + brow[1];
        v0.z = acc[i][2] + brow[2];
        v0.w = acc[i][3] + brow[3];
        v1.x = acc[i][4] + brow[4];
        v1.y = acc[i][5] + brow[5];
        v1.z = acc[i][6] + brow[6];
        v1.w = acc[i][7] + brow[7];
        *(float4*)(crow)     = v0;
        *(float4*)(crow + 4) = v1;
    }
}

// ---------------------------------------------------------------------------
// Phase 2: persistent recurrence. 128 blocks x 256 threads (8 warps).
// Block bid owns hidden units j0=8*bid (all 4 gates): 32 W rows in SMEM.
// Warp w computes batch rows [16w, 16w+16), all 32 n. Per step:
//   stage h chunk -> 4 gate mma per k8 -> fused epilogue -> grid barrier.
// Fragment mapping identical to round-3 verified kernel.
// ---------------------------------------------------------------------------
__global__ void __launch_bounds__(256)
lstm_persistent()
{
    extern __shared__ uint32_t smem[];
    uint32_t* sh_w = smem;                  // [32][WSTRIDE]
    uint32_t* sh_h = smem + 32 * WSTRIDE;   // [128][HSTRIDE]

    const int tid  = threadIdx.x;
    const int lane = tid & 31;
    const int warp = tid >> 5;              // 0..7
    const int j0   = blockIdx.x * 8;

    // Load W slice once: rows (g*8+jj) <- g_Whp[g*1024 + j0+jj][:]
    for (int idx = tid; idx < 32 * 1024; idx += 256) {
        int row = idx >> 10;
        int col = idx & 1023;
        int g   = row >> 3;
        int jj  = row & 7;
        sh_w[row * WSTRIDE + col] =
            g_Whp[(size_t)(g * H_ + j0 + jj) * H_ + col];
    }

    const int r  = lane >> 2;               // 0..7
    const int kq = lane & 3;                // 0..3
    const int jc = j0 + 2 * kq;

    // h chunk loader: 2 threads per row, 32 floats each
    const int hm = tid >> 1;                // 0..127
    const int hq = (tid & 1) * 32;          // 0 or 32

    const int arow0 = (warp * 16 + r) * HSTRIDE;
    const int arow1 = (warp * 16 + r + 8) * HSTRIDE;

    __syncthreads();   // sh_w ready

    for (int t = 0; t < T_; t++) {
        const float* __restrict__ h_in = g_h[t & 1];
        float* __restrict__ h_out      = g_h[(t + 1) & 1];

        float acc[4][4];
#pragma unroll
        for (int g = 0; g < 4; g++)
#pragma unroll
            for (int i = 0; i < 4; i++) acc[g][i] = 0.0f;

        for (int k0 = 0; k0 < H_; k0 += CHUNK) {
            // stage h chunk (fp32 -> tf32)
            const float* hrow = h_in + (size_t)hm * H_ + k0 + hq;
#pragma unroll
            for (int i = 0; i < 8; i++) {
                float4 v = *(const float4*)(hrow + i * 4);
                uint4 u;
                u.x = f2tf32(v.x); u.y = f2tf32(v.y);
                u.z = f2tf32(v.z); u.w = f2tf32(v.w);
                *(uint4*)&sh_h[hm * HSTRIDE + hq + i * 4] = u;
            }
            __syncthreads();

#pragma unroll
            for (int ks = 0; ks < 8; ks++) {
                const int kb = ks * 8;
                uint32_t a0 = sh_h[arow0 + kb + kq];
                uint32_t a1 = sh_h[arow1 + kb + kq];
                uint32_t a2 = sh_h[arow0 + kb + kq + 4];
                uint32_t a3 = sh_h[arow1 + kb + kq + 4];
#pragma unroll
                for (int g = 0; g < 4; g++) {
                    uint32_t b0 = sh_w[(g * 8 + r) * WSTRIDE + k0 + kb + kq];
                    uint32_t b1 = sh_w[(g * 8 + r) * WSTRIDE + k0 + kb + kq + 4];
                    mma_tf32(acc[g], a0, a1, a2, a3, b0, b1);
                }
            }
            __syncthreads();
        }

        // fused gate epilogue: lane holds rows {r, r+8}, cols {jc, jc+1}
#pragma unroll
        for (int rh = 0; rh < 2; rh++) {
            const int b = warp * 16 + r + rh * 8;
            const size_t m = (size_t)b * T_ + t;
            const float* gx = g_GX + m * G4_;
            float2 gxf = *(const float2*)(gx + 0 * H_ + jc);
            float2 gxi = *(const float2*)(gx + 1 * H_ + jc);
            float2 gxc = *(const float2*)(gx + 2 * H_ + jc);
            float2 gxo = *(const float2*)(gx + 3 * H_ + jc);
            float2 cold = *(const float2*)(g_c + b * H_ + jc);

            const int a0i = rh * 2, a1i = rh * 2 + 1;
            float f0 = sigmf(acc[0][a0i] + gxf.x);
            float f1 = sigmf(acc[0][a1i] + gxf.y);
            float i0 = sigmf(acc[1][a0i] + gxi.x);
            float i1 = sigmf(acc[1][a1i] + gxi.y);
            float t0 = tanhf(acc[2][a0i] + gxc.x);
            float t1 = tanhf(acc[2][a1i] + gxc.y);
            float o0 = sigmf(acc[3][a0i] + gxo.x);
            float o1 = sigmf(acc[3][a1i] + gxo.y);

            float cn0 = f0 * cold.x + i0 * t0;
            float cn1 = f1 * cold.y + i1 * t1;
            float hn0 = o0 * tanhf(cn0);
            float hn1 = o1 * tanhf(cn1);

            *(float2*)(g_c   + b * H_ + jc) = make_float2(cn0, cn1);
            *(float2*)(h_out + b * H_ + jc) = make_float2(hn0, hn1);
            *(float2*)(g_HS  + m * H_ + jc) = make_float2(hn0, hn1);
        }

        // grid barrier (all 128 blocks co-resident: 1 block/SM by smem size)
        __threadfence();
        __syncthreads();
        if (tid == 0) {
            const unsigned target = (unsigned)(t + 1) * NBLK;
            atomicAdd(&g_bar, 1u);
            unsigned v;
            do {
                asm volatile("ld.acquire.gpu.u32 %0, [%1];"
                             : "=r"(v) : "l"(&g_bar));
                if (v < target) __nanosleep(64);
            } while (v < target);
        }
        __syncthreads();
    }
}

// ---------------------------------------------------------------------------
// Host launcher
// ---------------------------------------------------------------------------
extern "C" void kernel_launch(void* const* d_in, const int* in_sizes, int n_in,
                              void* d_out, int out_size)
{
    (void)in_sizes; (void)n_in; (void)out_size;

    const float* x     = (const float*)d_in[0];
    const float* W_f   = (const float*)d_in[1];
    const float* b_f   = (const float*)d_in[2];
    const float* W_i   = (const float*)d_in[3];
    const float* b_i   = (const float*)d_in[4];
    const float* W_c   = (const float*)d_in[5];
    const float* b_c   = (const float*)d_in[6];
    const float* W_o   = (const float*)d_in[7];
    const float* b_o   = (const float*)d_in[8];
    const float* W_out = (const float*)d_in[9];
    const float* b_out = (const float*)d_in[10];
    float* out = (float*)d_out;

    void *p_wxp, *p_bp, *p_gx, *p_hs, *p_h, *p_c, *p_bar;
    cudaGetSymbolAddress(&p_wxp, g_Wxp);
    cudaGetSymbolAddress(&p_bp,  g_bp);
    cudaGetSymbolAddress(&p_gx,  g_GX);
    cudaGetSymbolAddress(&p_hs,  g_HS);
    cudaGetSymbolAddress(&p_h,   g_h);
    cudaGetSymbolAddress(&p_c,   g_c);
    cudaGetSymbolAddress(&p_bar, g_bar);

    // idempotent attribute set (no static guard; not a stream op, capture-safe)
    cudaFuncSetAttribute(lstm_persistent,
                         cudaFuncAttributeMaxDynamicSharedMemorySize,
                         SMEM_BYTES);

    // zero initial state + barrier counter (re-zeroed on every graph replay)
    cudaMemsetAsync(p_h, 0, (size_t)B_ * H_ * sizeof(float));
    cudaMemsetAsync(p_c, 0, (size_t)B_ * H_ * sizeof(float));
    cudaMemsetAsync(p_bar, 0, sizeof(unsigned));

    // Phase 0: pack weights (planar; Whp -> tf32)
    pack_weights<<<G4_, 128>>>(W_f, W_i, W_c, W_o, b_f, b_i, b_c, b_o);

    // Phase 1: GX = x @ Wxp^T + bp   (M=32768, N=4096, K=512)
    {
        dim3 grid(G4_ / 128, M_ / 128);
        sgemm_nt<<<grid, 256>>>(x, (const float*)p_wxp, (const float*)p_bp,
                                (float*)p_gx, M_, G4_, IN_);
    }

    // Phase 2: persistent recurrence (all 256 steps in one kernel)
    lstm_persistent<<<NBLK, 256, SMEM_BYTES>>>();

    // Phase 3: out = HS @ W_out^T + b_out  (M=32768, N=512, K=1024)
    {
        dim3 grid(OUT_ / 128, M_ / 128);
        sgemm_nt<<<grid, 256>>>((const float*)p_hs, W_out, b_out,
                                out, M_, OUT_, H_);
    }
}

// round 6
// speedup vs baseline: 1.4429x; 1.4429x over previous
#include <cuda_runtime.h>
#include <cuda_fp16.h>
#include <math.h>
#include <stdint.h>

// ---------------------------------------------------------------------------
// LSTM: B=128, T=256, In=512, H=1024, Out=512
// Phase 0: pack gate weights PLANAR n = g*1024 + j; Whp->tf32, Wxp->fp16.
//          cvt x -> fp16.
// Phase 1: GX = xh @ Wxph^T + bp        (fp16 tensor-core GEMM, fp32 accum)
// Phase 2: 256x lstm_step_mma           (tf32 mma + fused gate epilogue)
// Phase 3: out = HS @ W_out^T + b_out   (fp32 SIMT SGEMM)
// ---------------------------------------------------------------------------

#define B_   128
#define T_   256
#define IN_  512
#define H_   1024
#define G4_  4096
#define OUT_ 512
#define M_   (B_ * T_)      // 32768

__device__ uint32_t g_Whp [(size_t)G4_ * H_];   // packed h-part weights (tf32 bits)
__device__ __half   g_Wxph[(size_t)G4_ * IN_];  // packed x-part weights (fp16)
__device__ float    g_bp  [G4_];                // packed bias
__device__ __half   g_xh  [(size_t)M_ * IN_];   // x in fp16
__device__ float    g_GX  [(size_t)M_ * G4_];   // input-projection gates (fp32)
__device__ float    g_HS  [(size_t)M_ * H_];    // hidden states (all t)
__device__ float    g_h   [2][B_ * H_];         // ping-pong h
__device__ float    g_c   [B_ * H_];            // cell state

__device__ __forceinline__ float sigmf(float x) { return 1.0f / (1.0f + expf(-x)); }

__device__ __forceinline__ uint32_t f2tf32(float x) {
    uint32_t r;
    asm("cvt.rna.tf32.f32 %0, %1;" : "=r"(r) : "f"(x));
    return r;
}

__device__ __forceinline__ void mma_tf32(float c[4], uint32_t a0, uint32_t a1,
                                         uint32_t a2, uint32_t a3,
                                         uint32_t b0, uint32_t b1) {
    asm volatile(
        "mma.sync.aligned.m16n8k8.row.col.f32.tf32.tf32.f32 "
        "{%0,%1,%2,%3}, {%4,%5,%6,%7}, {%8,%9}, {%0,%1,%2,%3};"
        : "+f"(c[0]), "+f"(c[1]), "+f"(c[2]), "+f"(c[3])
        : "r"(a0), "r"(a1), "r"(a2), "r"(a3), "r"(b0), "r"(b1));
}

__device__ __forceinline__ void mma_f16(float c[4], uint32_t a0, uint32_t a1,
                                        uint32_t a2, uint32_t a3,
                                        uint32_t b0, uint32_t b1) {
    asm volatile(
        "mma.sync.aligned.m16n8k16.row.col.f32.f16.f16.f32 "
        "{%0,%1,%2,%3}, {%4,%5,%6,%7}, {%8,%9}, {%0,%1,%2,%3};"
        : "+f"(c[0]), "+f"(c[1]), "+f"(c[2]), "+f"(c[3])
        : "r"(a0), "r"(a1), "r"(a2), "r"(a3), "r"(b0), "r"(b1));
}

// ---------------------------------------------------------------------------
// Phase 0a: pack weights planar. blockIdx.x = n (0..4095). 128 threads.
// ---------------------------------------------------------------------------
__global__ void pack_weights(const float* __restrict__ Wf, const float* __restrict__ Wi,
                             const float* __restrict__ Wc, const float* __restrict__ Wo,
                             const float* __restrict__ bf, const float* __restrict__ bi,
                             const float* __restrict__ bc, const float* __restrict__ bo)
{
    int n = blockIdx.x;
    int g = n >> 10;
    int j = n & 1023;
    const float* W = (g == 0) ? Wf : (g == 1) ? Wi : (g == 2) ? Wc : Wo;
    const float* row = W + (size_t)j * (IN_ + H_);
    for (int k = threadIdx.x; k < IN_; k += blockDim.x)
        g_Wxph[(size_t)n * IN_ + k] = __float2half_rn(row[k]);
    for (int k = threadIdx.x; k < H_; k += blockDim.x)
        g_Whp[(size_t)n * H_ + k] = f2tf32(row[IN_ + k]);
    if (threadIdx.x == 0) {
        const float* bb = (g == 0) ? bf : (g == 1) ? bi : (g == 2) ? bc : bo;
        g_bp[n] = bb[j];
    }
}

// ---------------------------------------------------------------------------
// Phase 0b: fp32 -> fp16 bulk convert (4 elems/thread).
// ---------------------------------------------------------------------------
__global__ void cvt_f2h(const float* __restrict__ in, __half* __restrict__ out, int n4)
{
    int i = blockIdx.x * blockDim.x + threadIdx.x;
    if (i < n4) {
        float4 v = ((const float4*)in)[i];
        ((__half2*)out)[2 * i]     = __floats2half2_rn(v.x, v.y);
        ((__half2*)out)[2 * i + 1] = __floats2half2_rn(v.z, v.w);
    }
}

// ---------------------------------------------------------------------------
// Phase 1: fp16 tensor-core NT GEMM: C[M,N] = A[M,K] @ B[N,K]^T + bias[N].
// 128x128 tile, k-chunk 32, 256 threads = 8 warps, warp tile 32x64.
// SMEM as u32 (fp16x2 k-pairs), row stride HPAD=20 words (bank-safe: 20%32=20,
// lane bank = 4g+t pattern, all distinct).
// ---------------------------------------------------------------------------
#define HPAD 20

__global__ void __launch_bounds__(256)
hgemm_nt(const __half* __restrict__ A, const __half* __restrict__ Bm,
         const float* __restrict__ bias, float* __restrict__ C,
         int Ndim, int Kdim)
{
    __shared__ uint32_t sA[128 * HPAD];
    __shared__ uint32_t sB[128 * HPAD];

    const int tid  = threadIdx.x;
    const int m0   = blockIdx.y * 128;
    const int n0   = blockIdx.x * 128;
    const int lane = tid & 31;
    const int warp = tid >> 5;
    const int wm   = warp >> 1;         // 0..3  (32-row slab)
    const int wn   = warp & 1;          // 0..1  (64-col slab)
    const int g    = lane >> 2;         // 0..7
    const int t    = lane & 3;          // 0..3

    const int row  = tid >> 1;          // staging row 0..127
    const int half = tid & 1;           // staging k-half

    const __half* Arow = A + (size_t)(m0 + row) * Kdim + half * 16;
    const __half* Brow = Bm + (size_t)(n0 + row) * Kdim + half * 16;

    float acc[2][8][4];
#pragma unroll
    for (int mf = 0; mf < 2; mf++)
#pragma unroll
        for (int nf = 0; nf < 8; nf++)
#pragma unroll
            for (int i = 0; i < 4; i++) acc[mf][nf][i] = 0.0f;

    for (int k0 = 0; k0 < Kdim; k0 += 32) {
        // stage 128x32 fp16 of A and B (each thread: 16 fp16 = 2 uint4)
        uint4 a0v = *(const uint4*)(Arow + k0);
        uint4 a1v = *(const uint4*)(Arow + k0 + 8);
        uint4 b0v = *(const uint4*)(Brow + k0);
        uint4 b1v = *(const uint4*)(Brow + k0 + 8);
        *(uint4*)&sA[row * HPAD + half * 8]     = a0v;
        *(uint4*)&sA[row * HPAD + half * 8 + 4] = a1v;
        *(uint4*)&sB[row * HPAD + half * 8]     = b0v;
        *(uint4*)&sB[row * HPAD + half * 8 + 4] = b1v;
        __syncthreads();

#pragma unroll
        for (int ks = 0; ks < 2; ks++) {        // two k16 steps
            const int kb = ks * 8;              // u32 offset
            uint32_t a[2][4];
#pragma unroll
            for (int mf = 0; mf < 2; mf++) {
                const int ar = wm * 32 + mf * 16;
                a[mf][0] = sA[(ar + g)     * HPAD + kb + t];
                a[mf][1] = sA[(ar + g + 8) * HPAD + kb + t];
                a[mf][2] = sA[(ar + g)     * HPAD + kb + t + 4];
                a[mf][3] = sA[(ar + g + 8) * HPAD + kb + t + 4];
            }
#pragma unroll
            for (int nf = 0; nf < 8; nf++) {
                const int br = wn * 64 + nf * 8 + g;
                uint32_t b0 = sB[br * HPAD + kb + t];
                uint32_t b1 = sB[br * HPAD + kb + t + 4];
#pragma unroll
                for (int mf = 0; mf < 2; mf++)
                    mma_f16(acc[mf][nf], a[mf][0], a[mf][1], a[mf][2], a[mf][3], b0, b1);
            }
        }
        __syncthreads();
    }

    // epilogue: bias + fp32 stores (float2 per c-pair)
#pragma unroll
    for (int mf = 0; mf < 2; mf++) {
        const int rbase = m0 + wm * 32 + mf * 16;
#pragma unroll
        for (int nf = 0; nf < 8; nf++) {
            const int cbase = n0 + wn * 64 + nf * 8 + 2 * t;
            float bv0 = bias[cbase];
            float bv1 = bias[cbase + 1];
            *(float2*)&C[(size_t)(rbase + g) * Ndim + cbase] =
                make_float2(acc[mf][nf][0] + bv0, acc[mf][nf][1] + bv1);
            *(float2*)&C[(size_t)(rbase + g + 8) * Ndim + cbase] =
                make_float2(acc[mf][nf][2] + bv0, acc[mf][nf][3] + bv1);
        }
    }
}

// ---------------------------------------------------------------------------
// Phase 3: fp32 NT SGEMM: C[M,N] = A[M,K] * B[N,K]^T + bias[N]
// ---------------------------------------------------------------------------
__global__ void __launch_bounds__(256)
sgemm_nt(const float* __restrict__ A, const float* __restrict__ Bm,
         const float* __restrict__ bias, float* __restrict__ C,
         int Mdim, int Ndim, int Kdim)
{
    __shared__ float As[8][128];
    __shared__ float Bs[8][128];

    const int tid = threadIdx.x;
    const int m0 = blockIdx.y * 128;
    const int n0 = blockIdx.x * 128;

    const int ldRow = tid >> 1;
    const int ldK   = (tid & 1) * 4;

    const float* Aptr = A + (size_t)(m0 + ldRow) * Kdim + ldK;
    const float* Bptr = Bm + (size_t)(n0 + ldRow) * Kdim + ldK;

    const int ty = tid >> 4;
    const int tx = tid & 15;

    float acc[8][8];
#pragma unroll
    for (int i = 0; i < 8; i++)
#pragma unroll
        for (int j = 0; j < 8; j++) acc[i][j] = 0.0f;

    for (int k0 = 0; k0 < Kdim; k0 += 8) {
        float4 av = *(const float4*)(Aptr + k0);
        float4 bv = *(const float4*)(Bptr + k0);
        As[ldK + 0][ldRow] = av.x;
        As[ldK + 1][ldRow] = av.y;
        As[ldK + 2][ldRow] = av.z;
        As[ldK + 3][ldRow] = av.w;
        Bs[ldK + 0][ldRow] = bv.x;
        Bs[ldK + 1][ldRow] = bv.y;
        Bs[ldK + 2][ldRow] = bv.z;
        Bs[ldK + 3][ldRow] = bv.w;
        __syncthreads();

#pragma unroll
        for (int kk = 0; kk < 8; kk++) {
            float ar[8], br[8];
            *(float4*)(ar)     = *(const float4*)&As[kk][ty * 8];
            *(float4*)(ar + 4) = *(const float4*)&As[kk][ty * 8 + 4];
            *(float4*)(br)     = *(const float4*)&Bs[kk][tx * 8];
            *(float4*)(br + 4) = *(const float4*)&Bs[kk][tx * 8 + 4];
#pragma unroll
            for (int i = 0; i < 8; i++)
#pragma unroll
                for (int j = 0; j < 8; j++)
                    acc[i][j] = fmaf(ar[i], br[j], acc[i][j]);
        }
        __syncthreads();
    }

#pragma unroll
    for (int i = 0; i < 8; i++) {
        float* crow = C + (size_t)(m0 + ty * 8 + i) * Ndim + n0 + tx * 8;
        const float* brow = bias + n0 + tx * 8;
        float4 v0, v1;
        v0.x = acc[i][0] + brow[0];
        v0.y = acc[i][1] + brow[1];
        v0.z = acc[i][2] + brow[2];
        v0.w = acc[i][3] + brow[3];
        v1.x = acc[i][4] + brow[4];
        v1.y = acc[i][5] + brow[5];
        v1.z = acc[i][6] + brow[6];
        v1.w = acc[i][7] + brow[7];
        *(float4*)(crow)     = v0;
        *(float4*)(crow + 4) = v1;
    }
}

// ---------------------------------------------------------------------------
// Phase 2: one timestep via tensor cores (round-3 verified kernel, verbatim).
// grid = (128, 2). block = 128 threads (4 warps).
// ---------------------------------------------------------------------------
#define KC 32

__global__ void __launch_bounds__(128)
lstm_step_mma(int t)
{
    __shared__ uint32_t sh_h[64][36];   // [m local][k local], tf32 bits, padded
    __shared__ uint32_t sh_w[32][36];   // [g*8+jj][k local], tf32 bits, padded

    const int tid  = threadIdx.x;
    const int lane = tid & 31;
    const int warp = tid >> 5;
    const int j0    = blockIdx.x * 8;
    const int mbase = blockIdx.y * 64;

    const float* __restrict__ h_in = g_h[t & 1];
    float* __restrict__ h_out      = g_h[(t + 1) & 1];

    float acc[4][4];
#pragma unroll
    for (int g = 0; g < 4; g++)
#pragma unroll
        for (int i = 0; i < 4; i++) acc[g][i] = 0.0f;

    const int gj   = tid >> 2;
    const int wrow = (gj >> 3) * H_ + j0 + (gj & 7);
    const uint32_t* __restrict__ Wrow = g_Whp + (size_t)wrow * H_;
    const int wq = (tid & 3) * 4;

    const int hm = tid >> 1;
    const int hq = (tid & 1) * 16;
    const float* __restrict__ hrow = h_in + (size_t)(mbase + hm) * H_ + hq;

    const int r  = lane >> 2;
    const int kq = lane & 3;

    for (int k0 = 0; k0 < H_; k0 += KC) {
        uint4 w0 = *(const uint4*)(Wrow + k0 + wq);
        uint4 w1 = *(const uint4*)(Wrow + k0 + wq + 16);
        *(uint4*)&sh_w[gj][wq]      = w0;
        *(uint4*)&sh_w[gj][wq + 16] = w1;
#pragma unroll
        for (int i = 0; i < 4; i++) {
            float4 v = *(const float4*)(hrow + k0 + i * 4);
            uint4 u;
            u.x = f2tf32(v.x); u.y = f2tf32(v.y);
            u.z = f2tf32(v.z); u.w = f2tf32(v.w);
            *(uint4*)&sh_h[hm][hq + i * 4] = u;
        }
        __syncthreads();

#pragma unroll
        for (int ks = 0; ks < 4; ks++) {
            const int kb = ks * 8;
            uint32_t a0 = sh_h[warp * 16 + r    ][kb + kq];
            uint32_t a1 = sh_h[warp * 16 + r + 8][kb + kq];
            uint32_t a2 = sh_h[warp * 16 + r    ][kb + kq + 4];
            uint32_t a3 = sh_h[warp * 16 + r + 8][kb + kq + 4];
#pragma unroll
            for (int g = 0; g < 4; g++) {
                uint32_t b0 = sh_w[g * 8 + r][kb + kq];
                uint32_t b1 = sh_w[g * 8 + r][kb + kq + 4];
                mma_tf32(acc[g], a0, a1, a2, a3, b0, b1);
            }
        }
        __syncthreads();
    }

    const int jc = j0 + 2 * kq;
#pragma unroll
    for (int rh = 0; rh < 2; rh++) {
        const int b = mbase + warp * 16 + r + rh * 8;
        const size_t m = (size_t)b * T_ + t;
        const float* gx = g_GX + m * G4_;
        float2 gxf = *(const float2*)(gx + 0 * H_ + jc);
        float2 gxi = *(const float2*)(gx + 1 * H_ + jc);
        float2 gxc = *(const float2*)(gx + 2 * H_ + jc);
        float2 gxo = *(const float2*)(gx + 3 * H_ + jc);
        float2 cold = *(const float2*)(g_c + b * H_ + jc);

        const int a0i = rh * 2, a1i = rh * 2 + 1;
        float f0 = sigmf(acc[0][a0i] + gxf.x);
        float f1 = sigmf(acc[0][a1i] + gxf.y);
        float i0 = sigmf(acc[1][a0i] + gxi.x);
        float i1 = sigmf(acc[1][a1i] + gxi.y);
        float t0 = tanhf(acc[2][a0i] + gxc.x);
        float t1 = tanhf(acc[2][a1i] + gxc.y);
        float o0 = sigmf(acc[3][a0i] + gxo.x);
        float o1 = sigmf(acc[3][a1i] + gxo.y);

        float cn0 = f0 * cold.x + i0 * t0;
        float cn1 = f1 * cold.y + i1 * t1;
        float hn0 = o0 * tanhf(cn0);
        float hn1 = o1 * tanhf(cn1);

        *(float2*)(g_c   + b * H_ + jc) = make_float2(cn0, cn1);
        *(float2*)(h_out + b * H_ + jc) = make_float2(hn0, hn1);
        *(float2*)(g_HS  + m * H_ + jc) = make_float2(hn0, hn1);
    }
}

// ---------------------------------------------------------------------------
// Host launcher
// ---------------------------------------------------------------------------
extern "C" void kernel_launch(void* const* d_in, const int* in_sizes, int n_in,
                              void* d_out, int out_size)
{
    (void)in_sizes; (void)n_in; (void)out_size;

    const float* x     = (const float*)d_in[0];
    const float* W_f   = (const float*)d_in[1];
    const float* b_f   = (const float*)d_in[2];
    const float* W_i   = (const float*)d_in[3];
    const float* b_i   = (const float*)d_in[4];
    const float* W_c   = (const float*)d_in[5];
    const float* b_c   = (const float*)d_in[6];
    const float* W_o   = (const float*)d_in[7];
    const float* b_o   = (const float*)d_in[8];
    const float* W_out = (const float*)d_in[9];
    const float* b_out = (const float*)d_in[10];
    float* out = (float*)d_out;

    void *p_wxph, *p_bp, *p_xh, *p_gx, *p_hs, *p_h, *p_c;
    cudaGetSymbolAddress(&p_wxph, g_Wxph);
    cudaGetSymbolAddress(&p_bp,   g_bp);
    cudaGetSymbolAddress(&p_xh,   g_xh);
    cudaGetSymbolAddress(&p_gx,   g_GX);
    cudaGetSymbolAddress(&p_hs,   g_HS);
    cudaGetSymbolAddress(&p_h,    g_h);
    cudaGetSymbolAddress(&p_c,    g_c);

    // zero initial state; t=255 writes g_h[0], re-zeroed on every replay.
    cudaMemsetAsync(p_h, 0, (size_t)B_ * H_ * sizeof(float));
    cudaMemsetAsync(p_c, 0, (size_t)B_ * H_ * sizeof(float));

    // Phase 0: pack weights + convert x to fp16
    pack_weights<<<G4_, 128>>>(W_f, W_i, W_c, W_o, b_f, b_i, b_c, b_o);
    {
        int n4 = M_ * IN_ / 4;
        cvt_f2h<<<(n4 + 255) / 256, 256>>>(x, (__half*)p_xh, n4);
    }

    // Phase 1: GX = xh @ Wxph^T + bp   (fp16 tensor cores)
    {
        dim3 grid(G4_ / 128, M_ / 128);
        hgemm_nt<<<grid, 256>>>((const __half*)p_xh, (const __half*)p_wxph,
                                (const float*)p_bp, (float*)p_gx, G4_, IN_);
    }

    // Phase 2: 256 recurrent steps (tensor-core, fused epilogue)
    for (int t = 0; t < T_; t++) {
        dim3 grid(H_ / 8, 2);
        lstm_step_mma<<<grid, 128>>>(t);
    }

    // Phase 3: out = HS @ W_out^T + b_out  (M=32768, N=512, K=1024)
    {
        dim3 grid(OUT_ / 128, M_ / 128);
        sgemm_nt<<<grid, 256>>>((const float*)p_hs, W_out, b_out,
                                out, M_, OUT_, H_);
    }
}

// round 8
// speedup vs baseline: 2.2386x; 1.5515x over previous
#include <cuda_runtime.h>
#include <cuda_fp16.h>
#include <math.h>
#include <stdint.h>

// ---------------------------------------------------------------------------
// LSTM: B=128, T=256, In=512, H=1024, Out=512
// Phase 0: pack weights planar n = g*1024+j. Whp -> tf32 bits with k-permuted
//          columns (within each k8: p -> ((p&3)<<1)|(p>>2)) so mma fragment
//          (k, k+4) pairs are contiguous (LDS.64). Wxp -> fp16. x -> fp16.
// Phase 1: GX = xh @ Wxph^T + bp        (fp16 mma, fp32 accum)
// Phase 2: 256x lstm_step_mma: h kept as tf32 bits (permuted layout) in
//          ping-pong g_ht; cp.async double-buffered KC=64 pipeline; fused
//          gate epilogue writes c (fp32), HS (fp32, normal order), ht (tf32
//          permuted).
// Phase 3: out = HS @ W_out^T + b_out   (fp32 SIMT SGEMM)
// ---------------------------------------------------------------------------

#define B_   128
#define T_   256
#define IN_  512
#define H_   1024
#define G4_  4096
#define OUT_ 512
#define M_   (B_ * T_)      // 32768

#define KC    64            // k-chunk
#define SST   72            // smem row stride in u32 (64 + 8: conflict-free)
#define NCHUNK (H_ / KC)    // 16
// dynamic smem: h double buf 2*64*SST + w double buf 2*32*SST (u32)
#define DSM_WORDS (2 * 64 * SST + 2 * 32 * SST)
#define DSM_BYTES (DSM_WORDS * 4)

__device__ uint32_t g_Whp [(size_t)G4_ * H_];   // h-part weights, tf32 bits, k-permuted
__device__ __half   g_Wxph[(size_t)G4_ * IN_];  // x-part weights, fp16
__device__ float    g_bp  [G4_];                // packed bias
__device__ __half   g_xh  [(size_t)M_ * IN_];   // x in fp16
__device__ float    g_GX  [(size_t)M_ * G4_];   // input-projection gates (fp32)
__device__ float    g_HS  [(size_t)M_ * H_];    // hidden states, normal order (fp32)
__device__ uint32_t g_ht  [2][B_ * H_];         // ping-pong h, tf32 bits, k-permuted
__device__ float    g_c   [B_ * H_];            // cell state

__device__ __forceinline__ float sigmf(float x) { return 1.0f / (1.0f + expf(-x)); }

__device__ __forceinline__ uint32_t f2tf32(float x) {
    uint32_t r;
    asm("cvt.rna.tf32.f32 %0, %1;" : "=r"(r) : "f"(x));
    return r;
}

// within-k8 permutation: contiguous pair (2p', 2p'+1) holds orig (t, t+4)
__device__ __host__ __forceinline__ int kperm(int k) {
    int p = k & 7;
    return (k & ~7) | (((p & 3) << 1) | (p >> 2));
}

__device__ __forceinline__ void mma_tf32(float c[4], uint32_t a0, uint32_t a1,
                                         uint32_t a2, uint32_t a3,
                                         uint32_t b0, uint32_t b1) {
    asm volatile(
        "mma.sync.aligned.m16n8k8.row.col.f32.tf32.tf32.f32 "
        "{%0,%1,%2,%3}, {%4,%5,%6,%7}, {%8,%9}, {%0,%1,%2,%3};"
        : "+f"(c[0]), "+f"(c[1]), "+f"(c[2]), "+f"(c[3])
        : "r"(a0), "r"(a1), "r"(a2), "r"(a3), "r"(b0), "r"(b1));
}

__device__ __forceinline__ void mma_f16(float c[4], uint32_t a0, uint32_t a1,
                                        uint32_t a2, uint32_t a3,
                                        uint32_t b0, uint32_t b1) {
    asm volatile(
        "mma.sync.aligned.m16n8k16.row.col.f32.f16.f16.f32 "
        "{%0,%1,%2,%3}, {%4,%5,%6,%7}, {%8,%9}, {%0,%1,%2,%3};"
        : "+f"(c[0]), "+f"(c[1]), "+f"(c[2]), "+f"(c[3])
        : "r"(a0), "r"(a1), "r"(a2), "r"(a3), "r"(b0), "r"(b1));
}

__device__ __forceinline__ void cp_async16(void* smem_dst, const void* gmem_src) {
    uint32_t d = (uint32_t)__cvta_generic_to_shared(smem_dst);
    asm volatile("cp.async.cg.shared.global [%0], [%1], 16;"
                 :: "r"(d), "l"(gmem_src));
}
__device__ __forceinline__ void cp_commit() {
    asm volatile("cp.async.commit_group;");
}
template <int N>
__device__ __forceinline__ void cp_wait() {
    asm volatile("cp.async.wait_group %0;" :: "n"(N));
}

// ---------------------------------------------------------------------------
// Phase 0a: pack weights planar. blockIdx.x = n (0..4095). 128 threads.
// ---------------------------------------------------------------------------
__global__ void pack_weights(const float* __restrict__ Wf, const float* __restrict__ Wi,
                             const float* __restrict__ Wc, const float* __restrict__ Wo,
                             const float* __restrict__ bf, const float* __restrict__ bi,
                             const float* __restrict__ bc, const float* __restrict__ bo)
{
    int n = blockIdx.x;
    int g = n >> 10;
    int j = n & 1023;
    const float* W = (g == 0) ? Wf : (g == 1) ? Wi : (g == 2) ? Wc : Wo;
    const float* row = W + (size_t)j * (IN_ + H_);
    for (int k = threadIdx.x; k < IN_; k += blockDim.x)
        g_Wxph[(size_t)n * IN_ + k] = __float2half_rn(row[k]);
    for (int k = threadIdx.x; k < H_; k += blockDim.x)
        g_Whp[(size_t)n * H_ + kperm(k)] = f2tf32(row[IN_ + k]);
    if (threadIdx.x == 0) {
        const float* bb = (g == 0) ? bf : (g == 1) ? bi : (g == 2) ? bc : bo;
        g_bp[n] = bb[j];
    }
}

// ---------------------------------------------------------------------------
// Phase 0b: fp32 -> fp16 bulk convert (4 elems/thread).
// ---------------------------------------------------------------------------
__global__ void cvt_f2h(const float* __restrict__ in, __half* __restrict__ out, int n4)
{
    int i = blockIdx.x * blockDim.x + threadIdx.x;
    if (i < n4) {
        float4 v = ((const float4*)in)[i];
        ((__half2*)out)[2 * i]     = __floats2half2_rn(v.x, v.y);
        ((__half2*)out)[2 * i + 1] = __floats2half2_rn(v.z, v.w);
    }
}

// ---------------------------------------------------------------------------
// Phase 1: fp16 tensor-core NT GEMM (verified round 6)
// ---------------------------------------------------------------------------
#define HPAD 20

__global__ void __launch_bounds__(256)
hgemm_nt(const __half* __restrict__ A, const __half* __restrict__ Bm,
         const float* __restrict__ bias, float* __restrict__ C,
         int Ndim, int Kdim)
{
    __shared__ uint32_t sA[128 * HPAD];
    __shared__ uint32_t sB[128 * HPAD];

    const int tid  = threadIdx.x;
    const int m0   = blockIdx.y * 128;
    const int n0   = blockIdx.x * 128;
    const int lane = tid & 31;
    const int warp = tid >> 5;
    const int wm   = warp >> 1;
    const int wn   = warp & 1;
    const int g    = lane >> 2;
    const int t    = lane & 3;

    const int row  = tid >> 1;
    const int half = tid & 1;

    const __half* Arow = A + (size_t)(m0 + row) * Kdim + half * 16;
    const __half* Brow = Bm + (size_t)(n0 + row) * Kdim + half * 16;

    float acc[2][8][4];
#pragma unroll
    for (int mf = 0; mf < 2; mf++)
#pragma unroll
        for (int nf = 0; nf < 8; nf++)
#pragma unroll
            for (int i = 0; i < 4; i++) acc[mf][nf][i] = 0.0f;

    for (int k0 = 0; k0 < Kdim; k0 += 32) {
        uint4 a0v = *(const uint4*)(Arow + k0);
        uint4 a1v = *(const uint4*)(Arow + k0 + 8);
        uint4 b0v = *(const uint4*)(Brow + k0);
        uint4 b1v = *(const uint4*)(Brow + k0 + 8);
        *(uint4*)&sA[row * HPAD + half * 8]     = a0v;
        *(uint4*)&sA[row * HPAD + half * 8 + 4] = a1v;
        *(uint4*)&sB[row * HPAD + half * 8]     = b0v;
        *(uint4*)&sB[row * HPAD + half * 8 + 4] = b1v;
        __syncthreads();

#pragma unroll
        for (int ks = 0; ks < 2; ks++) {
            const int kb = ks * 8;
            uint32_t a[2][4];
#pragma unroll
            for (int mf = 0; mf < 2; mf++) {
                const int ar = wm * 32 + mf * 16;
                a[mf][0] = sA[(ar + g)     * HPAD + kb + t];
                a[mf][1] = sA[(ar + g + 8) * HPAD + kb + t];
                a[mf][2] = sA[(ar + g)     * HPAD + kb + t + 4];
                a[mf][3] = sA[(ar + g + 8) * HPAD + kb + t + 4];
            }
#pragma unroll
            for (int nf = 0; nf < 8; nf++) {
                const int br = wn * 64 + nf * 8 + g;
                uint32_t b0 = sB[br * HPAD + kb + t];
                uint32_t b1 = sB[br * HPAD + kb + t + 4];
#pragma unroll
                for (int mf = 0; mf < 2; mf++)
                    mma_f16(acc[mf][nf], a[mf][0], a[mf][1], a[mf][2], a[mf][3], b0, b1);
            }
        }
        __syncthreads();
    }

#pragma unroll
    for (int mf = 0; mf < 2; mf++) {
        const int rbase = m0 + wm * 32 + mf * 16;
#pragma unroll
        for (int nf = 0; nf < 8; nf++) {
            const int cbase = n0 + wn * 64 + nf * 8 + 2 * t;
            float bv0 = bias[cbase];
            float bv1 = bias[cbase + 1];
            *(float2*)&C[(size_t)(rbase + g) * Ndim + cbase] =
                make_float2(acc[mf][nf][0] + bv0, acc[mf][nf][1] + bv1);
            *(float2*)&C[(size_t)(rbase + g + 8) * Ndim + cbase] =
                make_float2(acc[mf][nf][2] + bv0, acc[mf][nf][3] + bv1);
        }
    }
}

// ---------------------------------------------------------------------------
// Phase 3: fp32 NT SGEMM (verified)
// ---------------------------------------------------------------------------
__global__ void __launch_bounds__(256)
sgemm_nt(const float* __restrict__ A, const float* __restrict__ Bm,
         const float* __restrict__ bias, float* __restrict__ C,
         int Mdim, int Ndim, int Kdim)
{
    __shared__ float As[8][128];
    __shared__ float Bs[8][128];

    const int tid = threadIdx.x;
    const int m0 = blockIdx.y * 128;
    const int n0 = blockIdx.x * 128;

    const int ldRow = tid >> 1;
    const int ldK   = (tid & 1) * 4;

    const float* Aptr = A + (size_t)(m0 + ldRow) * Kdim + ldK;
    const float* Bptr = Bm + (size_t)(n0 + ldRow) * Kdim + ldK;

    const int ty = tid >> 4;
    const int tx = tid & 15;

    float acc[8][8];
#pragma unroll
    for (int i = 0; i < 8; i++)
#pragma unroll
        for (int j = 0; j < 8; j++) acc[i][j] = 0.0f;

    for (int k0 = 0; k0 < Kdim; k0 += 8) {
        float4 av = *(const float4*)(Aptr + k0);
        float4 bv = *(const float4*)(Bptr + k0);
        As[ldK + 0][ldRow] = av.x;
        As[ldK + 1][ldRow] = av.y;
        As[ldK + 2][ldRow] = av.z;
        As[ldK + 3][ldRow] = av.w;
        Bs[ldK + 0][ldRow] = bv.x;
        Bs[ldK + 1][ldRow] = bv.y;
        Bs[ldK + 2][ldRow] = bv.z;
        Bs[ldK + 3][ldRow] = bv.w;
        __syncthreads();

#pragma unroll
        for (int kk = 0; kk < 8; kk++) {
            float ar[8], br[8];
            *(float4*)(ar)     = *(const float4*)&As[kk][ty * 8];
            *(float4*)(ar + 4) = *(const float4*)&As[kk][ty * 8 + 4];
            *(float4*)(br)     = *(const float4*)&Bs[kk][tx * 8];
            *(float4*)(br + 4) = *(const float4*)&Bs[kk][tx * 8 + 4];
#pragma unroll
            for (int i = 0; i < 8; i++)
#pragma unroll
                for (int j = 0; j < 8; j++)
                    acc[i][j] = fmaf(ar[i], br[j], acc[i][j]);
        }
        __syncthreads();
    }

#pragma unroll
    for (int i = 0; i < 8; i++) {
        float* crow = C + (size_t)(m0 + ty * 8 + i) * Ndim + n0 + tx * 8;
        const float* brow = bias + n0 + tx * 8;
        float4 v0, v1;
        v0.x = acc[i][0] + brow[0];
        v0.y = acc[i][1] + brow[1];
        v0.z = acc[i][2] + brow[2];
        v0.w = acc[i][3] + brow[3];
        v1.x = acc[i][4] + brow[4];
        v1.y = acc[i][5] + brow[5];
        v1.z = acc[i][6] + brow[6];
        v1.w = acc[i][7] + brow[7];
        *(float4*)(crow)     = v0;
        *(float4*)(crow + 4) = v1;
    }
}

// ---------------------------------------------------------------------------
// Phase 2: one timestep. grid (128 j-tiles, 2 m-halves), 128 threads (4 warps).
// cp.async double-buffered (KC=64), operands pre-tf32 + k-permuted -> all
// fragment loads are LDS.64. Fragment mapping identical to verified round 3.
// ---------------------------------------------------------------------------
__global__ void __launch_bounds__(128)
lstm_step_mma(int t)
{
    extern __shared__ uint32_t dsm[];
    uint32_t* hb[2] = { dsm, dsm + 64 * SST };
    uint32_t* wb[2] = { dsm + 2 * 64 * SST, dsm + 2 * 64 * SST + 32 * SST };

    const int tid  = threadIdx.x;
    const int lane = tid & 31;
    const int warp = tid >> 5;
    const int j0    = blockIdx.x * 8;
    const int mbase = blockIdx.y * 64;

    const uint32_t* __restrict__ ht_in = g_ht[t & 1];
    uint32_t* __restrict__ ht_out      = g_ht[(t + 1) & 1];

    const int r  = lane >> 2;           // 0..7
    const int kq = lane & 3;            // 0..3
    const int jc = j0 + 2 * kq;

    float acc[4][4];
#pragma unroll
    for (int g = 0; g < 4; g++)
#pragma unroll
        for (int i = 0; i < 4; i++) acc[g][i] = 0.0f;

    // --- staging lambda (cp.async), chunk k0 -> buffer bi ---
    auto stage = [&](int k0, int bi) {
        // h: 64 rows x 64 u32 = 1024 segs of 16B, 8 per thread
#pragma unroll
        for (int i = 0; i < 8; i++) {
            int s    = tid + 128 * i;
            int row  = s >> 4;
            int col4 = (s & 15) * 4;
            cp_async16(&hb[bi][row * SST + col4],
                       ht_in + (size_t)(mbase + row) * H_ + k0 + col4);
        }
        // W: 32 rows x 64 u32 = 512 segs, 4 per thread
#pragma unroll
        for (int i = 0; i < 4; i++) {
            int s    = tid + 128 * i;
            int row  = s >> 4;          // 0..31
            int col4 = (s & 15) * 4;
            int wg   = row >> 3;
            int jj   = row & 7;
            cp_async16(&wb[bi][row * SST + col4],
                       g_Whp + (size_t)(wg * H_ + j0 + jj) * H_ + k0 + col4);
        }
        cp_commit();
    };

    stage(0, 0);

    for (int c = 0; c < NCHUNK; c++) {
        if (c + 1 < NCHUNK) {
            stage((c + 1) * KC, (c + 1) & 1);
            cp_wait<1>();
        } else {
            cp_wait<0>();
        }
        __syncthreads();

        const uint32_t* hbuf = hb[c & 1];
        const uint32_t* wbuf = wb[c & 1];
        const int arow0 = (warp * 16 + r) * SST;
        const int arow1 = (warp * 16 + r + 8) * SST;

#pragma unroll
        for (int ks = 0; ks < 8; ks++) {
            const int kb = ks * 8 + 2 * kq;
            uint2 aA = *(const uint2*)&hbuf[arow0 + kb];   // (a0, a2)
            uint2 aB = *(const uint2*)&hbuf[arow1 + kb];   // (a1, a3)
#pragma unroll
            for (int g = 0; g < 4; g++) {
                uint2 bv = *(const uint2*)&wbuf[(g * 8 + r) * SST + kb];
                mma_tf32(acc[g], aA.x, aB.x, aA.y, aB.y, bv.x, bv.y);
            }
        }
        __syncthreads();
    }

    // fused gate epilogue: lane holds rows {r, r+8}, cols {jc, jc+1}
    const int pj   = jc & 7;                    // even (0,2,4,6)
    const int jb   = jc & ~7;
    const int p0   = ((pj & 3) << 1) | (pj >> 2);
    const int p1   = (((pj + 1) & 3) << 1) | ((pj + 1) >> 2);
#pragma unroll
    for (int rh = 0; rh < 2; rh++) {
        const int b = mbase + warp * 16 + r + rh * 8;
        const size_t m = (size_t)b * T_ + t;
        const float* gx = g_GX + m * G4_;
        float2 gxf = *(const float2*)(gx + 0 * H_ + jc);
        float2 gxi = *(const float2*)(gx + 1 * H_ + jc);
        float2 gxc = *(const float2*)(gx + 2 * H_ + jc);
        float2 gxo = *(const float2*)(gx + 3 * H_ + jc);
        float2 cold = *(const float2*)(g_c + b * H_ + jc);

        const int a0i = rh * 2, a1i = rh * 2 + 1;
        float f0 = sigmf(acc[0][a0i] + gxf.x);
        float f1 = sigmf(acc[0][a1i] + gxf.y);
        float i0 = sigmf(acc[1][a0i] + gxi.x);
        float i1 = sigmf(acc[1][a1i] + gxi.y);
        float t0 = tanhf(acc[2][a0i] + gxc.x);
        float t1 = tanhf(acc[2][a1i] + gxc.y);
        float o0 = sigmf(acc[3][a0i] + gxo.x);
        float o1 = sigmf(acc[3][a1i] + gxo.y);

        float cn0 = f0 * cold.x + i0 * t0;
        float cn1 = f1 * cold.y + i1 * t1;
        float hn0 = o0 * tanhf(cn0);
        float hn1 = o1 * tanhf(cn1);

        *(float2*)(g_c  + b * H_ + jc) = make_float2(cn0, cn1);
        *(float2*)(g_HS + m * H_ + jc) = make_float2(hn0, hn1);
        // tf32 bits, k-permuted layout for next step's A operand
        ht_out[(size_t)b * H_ + jb + p0] = f2tf32(hn0);
        ht_out[(size_t)b * H_ + jb + p1] = f2tf32(hn1);
    }
}

// ---------------------------------------------------------------------------
// Host launcher
// ---------------------------------------------------------------------------
extern "C" void kernel_launch(void* const* d_in, const int* in_sizes, int n_in,
                              void* d_out, int out_size)
{
    (void)in_sizes; (void)n_in; (void)out_size;

    const float* x     = (const float*)d_in[0];
    const float* W_f   = (const float*)d_in[1];
    const float* b_f   = (const float*)d_in[2];
    const float* W_i   = (const float*)d_in[3];
    const float* b_i   = (const float*)d_in[4];
    const float* W_c   = (const float*)d_in[5];
    const float* b_c   = (const float*)d_in[6];
    const float* W_o   = (const float*)d_in[7];
    const float* b_o   = (const float*)d_in[8];
    const float* W_out = (const float*)d_in[9];
    const float* b_out = (const float*)d_in[10];
    float* out = (float*)d_out;

    void *p_wxph, *p_bp, *p_xh, *p_gx, *p_hs, *p_ht, *p_c;
    cudaGetSymbolAddress(&p_wxph, g_Wxph);
    cudaGetSymbolAddress(&p_bp,   g_bp);
    cudaGetSymbolAddress(&p_xh,   g_xh);
    cudaGetSymbolAddress(&p_gx,   g_GX);
    cudaGetSymbolAddress(&p_hs,   g_HS);
    cudaGetSymbolAddress(&p_ht,   g_ht);
    cudaGetSymbolAddress(&p_c,    g_c);

    cudaFuncSetAttribute(lstm_step_mma,
                         cudaFuncAttributeMaxDynamicSharedMemorySize,
                         DSM_BYTES);

    // zero initial state; t=255 writes g_ht[0], re-zeroed on every replay.
    cudaMemsetAsync(p_ht, 0, (size_t)B_ * H_ * sizeof(uint32_t));
    cudaMemsetAsync(p_c,  0, (size_t)B_ * H_ * sizeof(float));

    // Phase 0: pack weights + convert x to fp16
    pack_weights<<<G4_, 128>>>(W_f, W_i, W_c, W_o, b_f, b_i, b_c, b_o);
    {
        int n4 = M_ * IN_ / 4;
        cvt_f2h<<<(n4 + 255) / 256, 256>>>(x, (__half*)p_xh, n4);
    }

    // Phase 1: GX = xh @ Wxph^T + bp   (fp16 tensor cores)
    {
        dim3 grid(G4_ / 128, M_ / 128);
        hgemm_nt<<<grid, 256>>>((const __half*)p_xh, (const __half*)p_wxph,
                                (const float*)p_bp, (float*)p_gx, G4_, IN_);
    }

    // Phase 2: 256 recurrent steps (pipelined tensor-core, fused epilogue)
    for (int t = 0; t < T_; t++) {
        dim3 grid(H_ / 8, 2);
        lstm_step_mma<<<grid, 128, DSM_BYTES>>>(t);
    }

    // Phase 3: out = HS @ W_out^T + b_out  (M=32768, N=512, K=1024)
    {
        dim3 grid(OUT_ / 128, M_ / 128);
        sgemm_nt<<<grid, 256>>>((const float*)p_hs, W_out, b_out,
                                out, M_, OUT_, H_);
    }
}

// round 9
// speedup vs baseline: 3.6025x; 1.6092x over previous
#include <cuda_runtime.h>
#include <cuda_fp16.h>
#include <math.h>
#include <stdint.h>

// ---------------------------------------------------------------------------
// LSTM: B=128, T=256, In=512, H=1024, Out=512
// Phase 0: pack weights planar n = g*1024+j. Whh -> fp16 half2 words, word-
//          permuted within each k16 group (w -> ((w&3)<<1)|((w>>2)&1)) so the
//          mma fragment word pair (t, t+4) is contiguous (LDS.64).
//          Wxp -> fp16. x -> fp16. W_out -> fp16.
// Phase 1: GX = xh @ Wxph^T + bp        (fp16 mma, fp32 accum)
// Phase 2: 256x lstm_step_mma: fp16 m16n8k16 recurrence; h ping-pong g_hth
//          (fp16, permuted); merged M (one block = all 128 rows, 8 warps);
//          triple-buffered cp.async (KC=128k); fused gate epilogue writes
//          c (fp32), HSh (fp16, natural order), hth (fp16 permuted).
// Phase 3: out = HSh @ W_outh^T + b_out (fp16 mma, fp32 accum + fp32 bias)
// ---------------------------------------------------------------------------

#define B_   128
#define T_   256
#define IN_  512
#define H_   1024
#define G4_  4096
#define OUT_ 512
#define M_   (B_ * T_)      // 32768
#define HW   512            // half2 words per H-length row

#define KCW    64           // k-chunk in half2 words (=128 k)
#define SST    72           // smem row stride in u32 words (64 + 8)
#define NCHUNK (HW / KCW)   // 8
// dynamic smem: 3 x (h 128*SST + w 32*SST) u32
#define DSM_WORDS (3 * (128 * SST + 32 * SST))
#define DSM_BYTES (DSM_WORDS * 4)

__device__ uint32_t g_Whh [(size_t)G4_ * HW];   // h-part weights, fp16 pairs, permuted
__device__ __half   g_Wxph[(size_t)G4_ * IN_];  // x-part weights, fp16
__device__ __half   g_Wouth[(size_t)OUT_ * H_]; // output weights, fp16
__device__ float    g_bp  [G4_];                // packed bias
__device__ __half   g_xh  [(size_t)M_ * IN_];   // x in fp16
__device__ float    g_GX  [(size_t)M_ * G4_];   // input-projection gates (fp32)
__device__ uint32_t g_HSh [(size_t)M_ * HW];    // hidden states fp16 (natural order)
__device__ uint32_t g_hth [2][B_ * HW];         // ping-pong h, fp16 pairs, permuted
__device__ float    g_c   [B_ * H_];            // cell state

__device__ __forceinline__ float sigmf(float x) { return 1.0f / (1.0f + expf(-x)); }

// word permutation within each 8-word (k16) group: pair (t, t+4) -> (2t, 2t+1)
__device__ __forceinline__ int wperm(int w) {
    return (w & ~7) | (((w & 3) << 1) | ((w >> 2) & 1));
}

__device__ __forceinline__ void mma_f16(float c[4], uint32_t a0, uint32_t a1,
                                        uint32_t a2, uint32_t a3,
                                        uint32_t b0, uint32_t b1) {
    asm volatile(
        "mma.sync.aligned.m16n8k16.row.col.f32.f16.f16.f32 "
        "{%0,%1,%2,%3}, {%4,%5,%6,%7}, {%8,%9}, {%0,%1,%2,%3};"
        : "+f"(c[0]), "+f"(c[1]), "+f"(c[2]), "+f"(c[3])
        : "r"(a0), "r"(a1), "r"(a2), "r"(a3), "r"(b0), "r"(b1));
}

__device__ __forceinline__ void cp_async16(void* smem_dst, const void* gmem_src) {
    uint32_t d = (uint32_t)__cvta_generic_to_shared(smem_dst);
    asm volatile("cp.async.cg.shared.global [%0], [%1], 16;"
                 :: "r"(d), "l"(gmem_src));
}
__device__ __forceinline__ void cp_commit() {
    asm volatile("cp.async.commit_group;");
}
template <int N>
__device__ __forceinline__ void cp_wait() {
    asm volatile("cp.async.wait_group %0;" :: "n"(N));
}

// ---------------------------------------------------------------------------
// Phase 0a: pack weights. blockIdx.x = n (0..4095). 128 threads.
// ---------------------------------------------------------------------------
__global__ void pack_weights(const float* __restrict__ Wf, const float* __restrict__ Wi,
                             const float* __restrict__ Wc, const float* __restrict__ Wo,
                             const float* __restrict__ bf, const float* __restrict__ bi,
                             const float* __restrict__ bc, const float* __restrict__ bo)
{
    int n = blockIdx.x;
    int g = n >> 10;
    int j = n & 1023;
    const float* W = (g == 0) ? Wf : (g == 1) ? Wi : (g == 2) ? Wc : Wo;
    const float* row = W + (size_t)j * (IN_ + H_);
    for (int k = threadIdx.x; k < IN_; k += blockDim.x)
        g_Wxph[(size_t)n * IN_ + k] = __float2half_rn(row[k]);
    for (int w = threadIdx.x; w < HW; w += blockDim.x) {
        __half2 v = __floats2half2_rn(row[IN_ + 2 * w], row[IN_ + 2 * w + 1]);
        g_Whh[(size_t)n * HW + wperm(w)] = *(uint32_t*)&v;
    }
    if (threadIdx.x == 0) {
        const float* bb = (g == 0) ? bf : (g == 1) ? bi : (g == 2) ? bc : bo;
        g_bp[n] = bb[j];
    }
}

// ---------------------------------------------------------------------------
// Phase 0b: fp32 -> fp16 bulk convert (4 elems/thread).
// ---------------------------------------------------------------------------
__global__ void cvt_f2h(const float* __restrict__ in, __half* __restrict__ out, int n4)
{
    int i = blockIdx.x * blockDim.x + threadIdx.x;
    if (i < n4) {
        float4 v = ((const float4*)in)[i];
        ((__half2*)out)[2 * i]     = __floats2half2_rn(v.x, v.y);
        ((__half2*)out)[2 * i + 1] = __floats2half2_rn(v.z, v.w);
    }
}

// ---------------------------------------------------------------------------
// Phases 1 & 3: fp16 tensor-core NT GEMM (verified round 6)
// C[M,N] = A[M,K] @ B[N,K]^T + bias[N], fp32 accum/out.
// ---------------------------------------------------------------------------
#define HPAD 20

__global__ void __launch_bounds__(256)
hgemm_nt(const __half* __restrict__ A, const __half* __restrict__ Bm,
         const float* __restrict__ bias, float* __restrict__ C,
         int Ndim, int Kdim)
{
    __shared__ uint32_t sA[128 * HPAD];
    __shared__ uint32_t sB[128 * HPAD];

    const int tid  = threadIdx.x;
    const int m0   = blockIdx.y * 128;
    const int n0   = blockIdx.x * 128;
    const int lane = tid & 31;
    const int warp = tid >> 5;
    const int wm   = warp >> 1;
    const int wn   = warp & 1;
    const int g    = lane >> 2;
    const int t    = lane & 3;

    const int row  = tid >> 1;
    const int half = tid & 1;

    const __half* Arow = A + (size_t)(m0 + row) * Kdim + half * 16;
    const __half* Brow = Bm + (size_t)(n0 + row) * Kdim + half * 16;

    float acc[2][8][4];
#pragma unroll
    for (int mf = 0; mf < 2; mf++)
#pragma unroll
        for (int nf = 0; nf < 8; nf++)
#pragma unroll
            for (int i = 0; i < 4; i++) acc[mf][nf][i] = 0.0f;

    for (int k0 = 0; k0 < Kdim; k0 += 32) {
        uint4 a0v = *(const uint4*)(Arow + k0);
        uint4 a1v = *(const uint4*)(Arow + k0 + 8);
        uint4 b0v = *(const uint4*)(Brow + k0);
        uint4 b1v = *(const uint4*)(Brow + k0 + 8);
        *(uint4*)&sA[row * HPAD + half * 8]     = a0v;
        *(uint4*)&sA[row * HPAD + half * 8 + 4] = a1v;
        *(uint4*)&sB[row * HPAD + half * 8]     = b0v;
        *(uint4*)&sB[row * HPAD + half * 8 + 4] = b1v;
        __syncthreads();

#pragma unroll
        for (int ks = 0; ks < 2; ks++) {
            const int kb = ks * 8;
            uint32_t a[2][4];
#pragma unroll
            for (int mf = 0; mf < 2; mf++) {
                const int ar = wm * 32 + mf * 16;
                a[mf][0] = sA[(ar + g)     * HPAD + kb + t];
                a[mf][1] = sA[(ar + g + 8) * HPAD + kb + t];
                a[mf][2] = sA[(ar + g)     * HPAD + kb + t + 4];
                a[mf][3] = sA[(ar + g + 8) * HPAD + kb + t + 4];
            }
#pragma unroll
            for (int nf = 0; nf < 8; nf++) {
                const int br = wn * 64 + nf * 8 + g;
                uint32_t b0 = sB[br * HPAD + kb + t];
                uint32_t b1 = sB[br * HPAD + kb + t + 4];
#pragma unroll
                for (int mf = 0; mf < 2; mf++)
                    mma_f16(acc[mf][nf], a[mf][0], a[mf][1], a[mf][2], a[mf][3], b0, b1);
            }
        }
        __syncthreads();
    }

#pragma unroll
    for (int mf = 0; mf < 2; mf++) {
        const int rbase = m0 + wm * 32 + mf * 16;
#pragma unroll
        for (int nf = 0; nf < 8; nf++) {
            const int cbase = n0 + wn * 64 + nf * 8 + 2 * t;
            float bv0 = bias[cbase];
            float bv1 = bias[cbase + 1];
            *(float2*)&C[(size_t)(rbase + g) * Ndim + cbase] =
                make_float2(acc[mf][nf][0] + bv0, acc[mf][nf][1] + bv1);
            *(float2*)&C[(size_t)(rbase + g + 8) * Ndim + cbase] =
                make_float2(acc[mf][nf][2] + bv0, acc[mf][nf][3] + bv1);
        }
    }
}

// ---------------------------------------------------------------------------
// Phase 2: one timestep, fp16 m16n8k16. grid = 128 j-tiles; 256 threads
// (8 warps, warp w -> rows [16w, 16w+16)). Triple-buffered cp.async, KC=128k.
// ---------------------------------------------------------------------------
__global__ void __launch_bounds__(256)
lstm_step_mma(int t)
{
    extern __shared__ uint32_t dsm[];
    uint32_t* hb[3] = { dsm, dsm + 128 * SST, dsm + 2 * 128 * SST };
    uint32_t* wbase = dsm + 3 * 128 * SST;
    uint32_t* wb[3] = { wbase, wbase + 32 * SST, wbase + 2 * 32 * SST };

    const int tid  = threadIdx.x;
    const int lane = tid & 31;
    const int warp = tid >> 5;          // 0..7
    const int j0   = blockIdx.x * 8;

    const uint32_t* __restrict__ ht_in = g_hth[t & 1];
    uint32_t* __restrict__ ht_out      = g_hth[(t + 1) & 1];

    const int r  = lane >> 2;           // 0..7
    const int kq = lane & 3;            // 0..3
    const int jc = j0 + 2 * kq;

    float acc[4][4];
#pragma unroll
    for (int g = 0; g < 4; g++)
#pragma unroll
        for (int i = 0; i < 4; i++) acc[g][i] = 0.0f;

    // --- staging (cp.async), chunk c -> buffer bi ---
    auto stage = [&](int c, int bi) {
        const int k0w = c * KCW;
        // h: 128 rows x 64 words = 2048 16B segs, 8 per thread
#pragma unroll
        for (int i = 0; i < 8; i++) {
            int s    = tid + 256 * i;
            int row  = s >> 4;
            int col4 = (s & 15) * 4;
            cp_async16(&hb[bi][row * SST + col4],
                       ht_in + (size_t)row * HW + k0w + col4);
        }
        // W: 32 rows x 64 words = 512 segs, 2 per thread
#pragma unroll
        for (int i = 0; i < 2; i++) {
            int s    = tid + 256 * i;
            int row  = s >> 4;          // 0..31
            int col4 = (s & 15) * 4;
            int wg   = row >> 3;
            int jj   = row & 7;
            cp_async16(&wb[bi][row * SST + col4],
                       g_Whh + (size_t)(wg * H_ + j0 + jj) * HW + k0w + col4);
        }
        cp_commit();
    };

    stage(0, 0);
    stage(1, 1);

    for (int c = 0; c < NCHUNK; c++) {
        if (c + 2 < NCHUNK) {
            stage(c + 2, (c + 2) % 3);
            cp_wait<2>();
        } else if (c + 2 == NCHUNK) {
            cp_wait<1>();
        } else {
            cp_wait<0>();
        }
        __syncthreads();

        const uint32_t* hbuf = hb[c % 3];
        const uint32_t* wbuf = wb[c % 3];
        const int arow0 = (warp * 16 + r) * SST;
        const int arow1 = (warp * 16 + r + 8) * SST;

#pragma unroll
        for (int ks = 0; ks < 8; ks++) {        // 8 k16 groups per chunk
            const int kb = ks * 8 + 2 * kq;
            uint2 aA = *(const uint2*)&hbuf[arow0 + kb];   // (a0, a2)
            uint2 aB = *(const uint2*)&hbuf[arow1 + kb];   // (a1, a3)
#pragma unroll
            for (int g = 0; g < 4; g++) {
                uint2 bv = *(const uint2*)&wbuf[(g * 8 + r) * SST + kb];
                mma_f16(acc[g], aA.x, aB.x, aA.y, aB.y, bv.x, bv.y);
            }
        }
        __syncthreads();
    }

    // fused gate epilogue: lane holds rows {16w+r, 16w+r+8}, cols {jc, jc+1}
    const int w    = (j0 >> 1) + kq;            // natural word index jc/2
    const int pw   = (w & ~7) | (((w & 3) << 1) | ((w >> 2) & 1));
#pragma unroll
    for (int rh = 0; rh < 2; rh++) {
        const int b = warp * 16 + r + rh * 8;
        const size_t m = (size_t)b * T_ + t;
        const float* gx = g_GX + m * G4_;
        float2 gxf = *(const float2*)(gx + 0 * H_ + jc);
        float2 gxi = *(const float2*)(gx + 1 * H_ + jc);
        float2 gxc = *(const float2*)(gx + 2 * H_ + jc);
        float2 gxo = *(const float2*)(gx + 3 * H_ + jc);
        float2 cold = *(const float2*)(g_c + b * H_ + jc);

        const int a0i = rh * 2, a1i = rh * 2 + 1;
        float f0 = sigmf(acc[0][a0i] + gxf.x);
        float f1 = sigmf(acc[0][a1i] + gxf.y);
        float i0 = sigmf(acc[1][a0i] + gxi.x);
        float i1 = sigmf(acc[1][a1i] + gxi.y);
        float t0 = tanhf(acc[2][a0i] + gxc.x);
        float t1 = tanhf(acc[2][a1i] + gxc.y);
        float o0 = sigmf(acc[3][a0i] + gxo.x);
        float o1 = sigmf(acc[3][a1i] + gxo.y);

        float cn0 = f0 * cold.x + i0 * t0;
        float cn1 = f1 * cold.y + i1 * t1;
        float hn0 = o0 * tanhf(cn0);
        float hn1 = o1 * tanhf(cn1);

        *(float2*)(g_c + b * H_ + jc) = make_float2(cn0, cn1);

        __half2 hp = __floats2half2_rn(hn0, hn1);
        g_HSh[m * HW + (jc >> 1)] = *(uint32_t*)&hp;          // natural order
        ht_out[(size_t)b * HW + pw] = *(uint32_t*)&hp;        // permuted order
    }
}

// ---------------------------------------------------------------------------
// Host launcher
// ---------------------------------------------------------------------------
extern "C" void kernel_launch(void* const* d_in, const int* in_sizes, int n_in,
                              void* d_out, int out_size)
{
    (void)in_sizes; (void)n_in; (void)out_size;

    const float* x     = (const float*)d_in[0];
    const float* W_f   = (const float*)d_in[1];
    const float* b_f   = (const float*)d_in[2];
    const float* W_i   = (const float*)d_in[3];
    const float* b_i   = (const float*)d_in[4];
    const float* W_c   = (const float*)d_in[5];
    const float* b_c   = (const float*)d_in[6];
    const float* W_o   = (const float*)d_in[7];
    const float* b_o   = (const float*)d_in[8];
    const float* W_out = (const float*)d_in[9];
    const float* b_out = (const float*)d_in[10];
    float* out = (float*)d_out;

    void *p_wxph, *p_wouth, *p_bp, *p_xh, *p_gx, *p_hsh, *p_ht, *p_c;
    cudaGetSymbolAddress(&p_wxph,  g_Wxph);
    cudaGetSymbolAddress(&p_wouth, g_Wouth);
    cudaGetSymbolAddress(&p_bp,    g_bp);
    cudaGetSymbolAddress(&p_xh,    g_xh);
    cudaGetSymbolAddress(&p_gx,    g_GX);
    cudaGetSymbolAddress(&p_hsh,   g_HSh);
    cudaGetSymbolAddress(&p_ht,    g_hth);
    cudaGetSymbolAddress(&p_c,     g_c);

    cudaFuncSetAttribute(lstm_step_mma,
                         cudaFuncAttributeMaxDynamicSharedMemorySize,
                         DSM_BYTES);

    // zero initial state; t=255 writes g_hth[0], re-zeroed on every replay.
    cudaMemsetAsync(p_ht, 0, (size_t)B_ * HW * sizeof(uint32_t));
    cudaMemsetAsync(p_c,  0, (size_t)B_ * H_ * sizeof(float));

    // Phase 0: pack weights + convert x and W_out to fp16
    pack_weights<<<G4_, 128>>>(W_f, W_i, W_c, W_o, b_f, b_i, b_c, b_o);
    {
        int n4 = M_ * IN_ / 4;
        cvt_f2h<<<(n4 + 255) / 256, 256>>>(x, (__half*)p_xh, n4);
        int w4 = OUT_ * H_ / 4;
        cvt_f2h<<<(w4 + 255) / 256, 256>>>(W_out, (__half*)p_wouth, w4);
    }

    // Phase 1: GX = xh @ Wxph^T + bp   (fp16 tensor cores)
    {
        dim3 grid(G4_ / 128, M_ / 128);
        hgemm_nt<<<grid, 256>>>((const __half*)p_xh, (const __half*)p_wxph,
                                (const float*)p_bp, (float*)p_gx, G4_, IN_);
    }

    // Phase 2: 256 recurrent steps (fp16 mma, triple-buffered, fused epilogue)
    for (int t = 0; t < T_; t++) {
        lstm_step_mma<<<128, 256, DSM_BYTES>>>(t);
    }

    // Phase 3: out = HSh @ W_outh^T + b_out  (fp16 tensor cores)
    {
        dim3 grid(OUT_ / 128, M_ / 128);
        hgemm_nt<<<grid, 256>>>((const __half*)p_hsh, (const __half*)p_wouth,
                                b_out, out, OUT_, H_);
    }
}